// round 15
// baseline (speedup 1.0000x reference)
#include <cuda_runtime.h>
#include <cuda_bf16.h>
#include <cuda_fp16.h>
#include <math.h>
#include <stdint.h>

// ---------------- problem-size bounds ----------------
#define NMAX 50048
#define EMAX 760064            // E + up to 3 pad slots per node
#define GMAX 2048

typedef __nv_bfloat16 bf16;
typedef __nv_bfloat162 bf162;

// ---------------- scratch (device globals) ----------------
// Invariant: g_deg and g_total are zero at entry of every launch.
__device__ int      g_deg[NMAX];
__device__ int      g_off[NMAX];
__device__ int      g_pos[NMAX];
__device__ int      g_total;
__device__ uint16_t g_srt_src[EMAX];

__device__ bf16    g_M [NMAX * 128];         // M1 (bf16); later reused as AB3 (fp8)
__device__ uint8_t g_AB[(NMAX + 1) * 256];   // fp8 e4m3 AB1/AB2 (+pad row)

// bf16 weights, transposed to [H][K] (n-major)
__device__ bf16  g_Wtn [64 * 32];
__device__ bf16  g_Wct1[256 * 64];
__device__ bf16  g_Wt1b[128 * 128];
__device__ bf16  g_Wct2[128 * 128];
__device__ bf16  g_Wt2b[64 * 64];
__device__ bf16  g_Wct3[64 * 64];
__device__ bf16  g_Wt3b[32 * 32];
__device__ float g_bc1[256], g_bc2[128], g_bc3[64];

__device__ float g_pool[GMAX * 32];
__device__ float g_gcnt[GMAX];

// ---------------- fp8 / async helpers ----------------
__device__ __forceinline__ uint16_t pack_e4m3(float v0, float v1) {
    uint16_t r;
    asm("cvt.rn.satfinite.e4m3x2.f32 %0, %1, %2;" : "=h"(r) : "f"(v1), "f"(v0));
    return r;
}
__device__ __forceinline__ __half2 e4_h2(uint16_t u) {
    uint32_t h;
    asm("cvt.rn.f16x2.e4m3x2 %0, %1;" : "=r"(h) : "h"(u));
    return *(__half2*)&h;
}
__device__ __forceinline__ void cp16(uint32_t saddr, const void* g) {
    asm volatile("cp.async.cg.shared.global [%0], [%1], 16;" :: "r"(saddr), "l"(g));
}
__device__ __forceinline__ void cp_commit() { asm volatile("cp.async.commit_group;"); }
__device__ __forceinline__ void cp_wait0()  { asm volatile("cp.async.wait_group 0;"); }

// -------- init: zero pool/gcnt, histogram degrees, prep weights --------
__global__ void init_kernel(const int* __restrict__ dst, int n, int e, int g,
                            const float* Wn,  const float* W1a, const float* b1a,
                            const float* W1b, const float* W2a, const float* b2a,
                            const float* W2b, const float* W3a, const float* b3a,
                            const float* W3b) {
    int i = blockIdx.x * blockDim.x + threadIdx.x;
    if (i < g * 32)  g_pool[i] = 0.f;
    if (i < g)       g_gcnt[i] = 0.f;
    if (i < e)       atomicAdd(&g_deg[dst[i]], 1);

    const int S0 = 64 * 32;
    const int S1 = 256 * 64;
    const int S2 = 128 * 128;
    const int S3 = 128 * 128;
    const int S4 = 64 * 64;
    const int S5 = 64 * 64;
    const int S6 = 32 * 32;
    const int TOT = S0 + S1 + S2 + S3 + S4 + S5 + S6;
    if (i < TOT) {
        int j = i;
        if (j < S0) { int c = j / 32, k = j % 32;
            g_Wtn[j] = __float2bfloat16(Wn[k * 64 + c]); return; } j -= S0;
        if (j < S1) { int c = j / 64, k = j % 64;
            float v = (c < 128) ? W1a[k * 128 + c] - W1a[(k + 64) * 128 + c]
                                : W1a[(k + 64) * 128 + (c - 128)];
            g_Wct1[j] = __float2bfloat16(v);
            if (k == 0) g_bc1[c] = (c < 128) ? b1a[c] : 0.f;
            return; } j -= S1;
        if (j < S2) { int c = j / 128, k = j % 128;
            g_Wt1b[j] = __float2bfloat16(W1b[k * 128 + c]); return; } j -= S2;
        if (j < S3) { int c = j / 128, k = j % 128;
            float v = (c < 64) ? W2a[k * 64 + c] - W2a[(k + 128) * 64 + c]
                               : W2a[(k + 128) * 64 + (c - 64)];
            g_Wct2[j] = __float2bfloat16(v);
            if (k == 0) g_bc2[c] = (c < 64) ? b2a[c] : 0.f;
            return; } j -= S3;
        if (j < S4) { int c = j / 64, k = j % 64;
            g_Wt2b[j] = __float2bfloat16(W2b[k * 64 + c]); return; } j -= S4;
        if (j < S5) { int c = j / 64, k = j % 64;
            float v = (c < 32) ? W3a[k * 32 + c] - W3a[(k + 64) * 32 + c]
                               : W3a[(k + 64) * 32 + (c - 32)];
            g_Wct3[j] = __float2bfloat16(v);
            if (k == 0) g_bc3[c] = (c < 32) ? b3a[c] : 0.f;
            return; } j -= S5;
        { int c = j / 32, k = j % 32;
            g_Wt3b[j] = __float2bfloat16(W3b[k * 32 + c]); }
    }
}

// Warp-aggregated range allocation (sizes rounded to multiples of 4) +
// pad-slot fill (sentinel index = n) + per-graph node counts.
__global__ void alloc_kernel(int n, const int* __restrict__ batch) {
    int i = blockIdx.x * blockDim.x + threadIdx.x;
    int lane = threadIdx.x & 31;
    int d  = (i < n) ? g_deg[i] : 0;
    int dr = (d + 3) & ~3;
    int pre = dr;
    #pragma unroll
    for (int s = 1; s < 32; s <<= 1) {
        int t = __shfl_up_sync(0xffffffffu, pre, s);
        if (lane >= s) pre += t;
    }
    int wsum = __shfl_sync(0xffffffffu, pre, 31);
    int base = 0;
    if (lane == 31) base = atomicAdd(&g_total, wsum);
    base = __shfl_sync(0xffffffffu, base, 31);
    int off = base + pre - dr;
    if (i < n) {
        g_off[i] = off; g_pos[i] = off;
        for (int p = d; p < dr; p++) g_srt_src[off + p] = (uint16_t)n;
        atomicAdd(&g_gcnt[batch[i]], 1.f);
    }
}

// ---------------- bf16 mma ----------------
__device__ __forceinline__ void mma_bf16(float* c, const uint32_t* a, const uint32_t* b) {
    asm volatile(
        "mma.sync.aligned.m16n8k16.row.col.f32.bf16.bf16.f32 "
        "{%0,%1,%2,%3}, {%4,%5,%6,%7}, {%8,%9}, {%0,%1,%2,%3};"
        : "+f"(c[0]), "+f"(c[1]), "+f"(c[2]), "+f"(c[3])
        : "r"(a[0]), "r"(a[1]), "r"(a[2]), "r"(a[3]), "r"(b[0]), "r"(b[1]));
}

// ---- edge-agg core: mean_e relu(A[w]+B[src_e]) for one node slice ----
// Lane owns 4 fp8 values at column sl*4 of a K1-wide feature row.
// Returns packed bf16x2 pair (4 values) in a uint2.
template <int K1>
__device__ __forceinline__ uint2 agg_node(const uint8_t* __restrict__ ABp,
                                          int w, int sl) {
    uint32_t a32 = *(const uint32_t*)(ABp + (size_t)w * 2 * K1 + sl * 4);
    __half2 aL = e4_h2((uint16_t)a32);
    __half2 aH = e4_h2((uint16_t)(a32 >> 16));
    const __half2 one = __float2half2_rn(1.f);
    __half2 accL = __float2half2_rn(0.f), accH = accL;

    int st = g_off[w];
    int d  = g_deg[w];
    int dr = (d + 3) & ~3;
    int en = st + dr;
    int e  = st;

    for (; e + 8 <= en; e += 8) {
        uint2 iv0 = *(const uint2*)&g_srt_src[e];
        uint2 iv1 = *(const uint2*)&g_srt_src[e + 4];
        int s0 = iv0.x & 0xffff, s1 = iv0.x >> 16;
        int s2 = iv0.y & 0xffff, s3 = iv0.y >> 16;
        int s4 = iv1.x & 0xffff, s5 = iv1.x >> 16;
        int s6 = iv1.y & 0xffff, s7 = iv1.y >> 16;
        uint32_t b0 = *(const uint32_t*)(ABp + (size_t)s0 * 2 * K1 + K1 + sl * 4);
        uint32_t b1 = *(const uint32_t*)(ABp + (size_t)s1 * 2 * K1 + K1 + sl * 4);
        uint32_t b2 = *(const uint32_t*)(ABp + (size_t)s2 * 2 * K1 + K1 + sl * 4);
        uint32_t b3 = *(const uint32_t*)(ABp + (size_t)s3 * 2 * K1 + K1 + sl * 4);
        uint32_t b4 = *(const uint32_t*)(ABp + (size_t)s4 * 2 * K1 + K1 + sl * 4);
        uint32_t b5 = *(const uint32_t*)(ABp + (size_t)s5 * 2 * K1 + K1 + sl * 4);
        uint32_t b6 = *(const uint32_t*)(ABp + (size_t)s6 * 2 * K1 + K1 + sl * 4);
        uint32_t b7 = *(const uint32_t*)(ABp + (size_t)s7 * 2 * K1 + K1 + sl * 4);
        #pragma unroll
        for (int q = 0; q < 8; q++) {
            uint32_t bq = (q == 0) ? b0 : (q == 1) ? b1 : (q == 2) ? b2 :
                          (q == 3) ? b3 : (q == 4) ? b4 : (q == 5) ? b5 :
                          (q == 6) ? b6 : b7;
            accL = __hadd2(accL, __hfma2_relu(one, e4_h2((uint16_t)bq), aL));
            accH = __hadd2(accH, __hfma2_relu(one, e4_h2((uint16_t)(bq >> 16)), aH));
        }
    }
    if (e < en) {
        uint2 iv = *(const uint2*)&g_srt_src[e];
        int s0 = iv.x & 0xffff, s1 = iv.x >> 16;
        int s2 = iv.y & 0xffff, s3 = iv.y >> 16;
        uint32_t b0 = *(const uint32_t*)(ABp + (size_t)s0 * 2 * K1 + K1 + sl * 4);
        uint32_t b1 = *(const uint32_t*)(ABp + (size_t)s1 * 2 * K1 + K1 + sl * 4);
        uint32_t b2 = *(const uint32_t*)(ABp + (size_t)s2 * 2 * K1 + K1 + sl * 4);
        uint32_t b3 = *(const uint32_t*)(ABp + (size_t)s3 * 2 * K1 + K1 + sl * 4);
        #pragma unroll
        for (int q = 0; q < 4; q++) {
            uint32_t bq = (q == 0) ? b0 : (q == 1) ? b1 : (q == 2) ? b2 : b3;
            accL = __hadd2(accL, __hfma2_relu(one, e4_h2((uint16_t)bq), aL));
            accH = __hadd2(accH, __hfma2_relu(one, e4_h2((uint16_t)(bq >> 16)), aH));
        }
    }

    float2 fL = __half22float2(accL);
    float2 fH = __half22float2(accH);
    float inv = 1.f / (float)max(d, 1);
    bf162 o01 = __floats2bfloat162_rn(fL.x * inv, fL.y * inv);
    bf162 o23 = __floats2bfloat162_rn(fH.x * inv, fH.y * inv);
    uint2 ov;
    ov.x = *(uint32_t*)&o01;
    ov.y = *(uint32_t*)&o23;
    return ov;
}

// agg a 64-node tile into SMEM (uint32 rows, stride RSA). All 8 warps.
template <int K1, int RSA>
__device__ __forceinline__ void agg_tile(const uint8_t* __restrict__ ABp,
                                         int row0, uint32_t* __restrict__ sM) {
    constexpr int LPN = K1 / 4;
    constexpr int NPW = 32 / LPN;
    const int tid  = threadIdx.x;
    const int wid  = tid >> 5;
    const int lane = tid & 31;
    const int sub  = lane / LPN;
    const int sl   = lane % LPN;
    #pragma unroll
    for (int pass = 0; pass < 8 / NPW; pass++) {
        int row = wid * 8 + pass * NPW + sub;
        uint2 ov = agg_node<K1>(ABp, row0 + row, sl);
        *(uint2*)&sM[row * RSA + sl * 2] = ov;
    }
}

// ======== persistent fused 2-stage GEMM (+ optional edge scatter) ====
template <int K1, int H1, int WOUT, int EPI1, int NSPLIT, int MINB, bool SCAT, bool XF32>
__global__ __launch_bounds__(256, MINB)
void fused_gemm(const void* __restrict__ Xv, const bf16* __restrict__ W1t,
                const float* __restrict__ b1, const float* __restrict__ gam,
                const float* __restrict__ bet, const bf16* __restrict__ W2t,
                const float* __restrict__ b2, uint8_t* __restrict__ AB,
                const int* __restrict__ esrc, const int* __restrict__ edst,
                int ne, int nrows, int ntiles) {
    constexpr int RSA  = K1 / 2 + 4;
    constexpr int RSB  = H1 / 2 + 4;
    constexpr int ST   = H1 + 8;
    constexpr int NJ1  = H1 / 16;
    constexpr int NJ2  = WOUT / 16;
    constexpr int NJ2H = NJ2 / NSPLIT;
    constexpr int SOS  = WOUT + 16;
    constexpr int XC   = K1 / 8;

    extern __shared__ uint32_t dyn[];
    uint32_t* sW1 = dyn;
    uint32_t* sW2 = sW1 + H1 * RSA;
    uint32_t* sA0 = sW2 + WOUT * RSB;
    bf16*     sT  = (bf16*)(sA0 + 64 * RSA);
    uint8_t*  sOut = (uint8_t*)(sT + 64 * ST);

    const int tid  = threadIdx.x;
    const int lane = tid & 31;
    const int wid  = tid >> 5;
    const int wm   = wid & 3;
    const int wn   = wid >> 2;
    const int gq   = lane >> 2;
    const int t4   = lane & 3;

    for (int i = tid; i < H1 * (K1 / 8); i += 256) {
        int row = i / (K1 / 8), q = i % (K1 / 8);
        *(uint4*)&sW1[row * RSA + q * 4] = *(const uint4*)&W1t[(size_t)row * K1 + q * 8];
    }
    for (int i = tid; i < WOUT * (H1 / 8); i += 256) {
        int row = i / (H1 / 8), q = i % (H1 / 8);
        *(uint4*)&sW2[row * RSB + q * 4] = *(const uint4*)&W2t[(size_t)row * H1 + q * 8];
    }
    if (blockIdx.x == 0 && tid < WOUT / 4)
        ((uint32_t*)AB)[(size_t)nrows * (WOUT / 4) + tid] = 0xFEFEFEFEu;

    if (SCAT) {   // independent of GEMM; consumed next launch
        for (int i = blockIdx.x * 256 + tid; i < ne; i += gridDim.x * 256) {
            int p = atomicAdd(&g_pos[edst[i]], 1);
            g_srt_src[p] = (uint16_t)esrc[i];
        }
    }

    const uint32_t sA0a = (uint32_t)__cvta_generic_to_shared(sA0);
    const float rsc = rsqrtf(1.f + 1e-5f);

    for (int tile = blockIdx.x; tile < ntiles; tile += gridDim.x) {
        const int row0 = tile * 64;

        __syncthreads();       // prev consumers of sA/sOut done
        if (XF32) {
            const float* Xf = (const float*)Xv;
            for (int i = tid; i < 64 * (K1 / 4); i += 256) {
                int row = i / (K1 / 4), q = i % (K1 / 4);
                int gr = row0 + row;
                float4 v = make_float4(0.f, 0.f, 0.f, 0.f);
                if (gr < nrows) v = *(const float4*)&Xf[(size_t)gr * K1 + q * 4];
                bf162 p0 = __floats2bfloat162_rn(v.x, v.y);
                bf162 p1 = __floats2bfloat162_rn(v.z, v.w);
                uint2 u;
                u.x = *(uint32_t*)&p0;
                u.y = *(uint32_t*)&p1;
                *(uint2*)&sA0[row * RSA + q * 2] = u;
            }
        } else {
            const bf16* Xb = (const bf16*)Xv;
            for (int i = tid; i < 64 * XC; i += 256) {
                int row = i / XC, q = i % XC;
                cp16(sA0a + (uint32_t)(row * RSA + q * 4) * 4,
                     &Xb[(size_t)(row0 + row) * K1 + q * 8]);
            }
            cp_commit();
            cp_wait0();
        }
        __syncthreads();

        // ---- stage 1 ----
        float acc1[NJ1][4];
        #pragma unroll
        for (int nj = 0; nj < NJ1; nj++)
            #pragma unroll
            for (int q = 0; q < 4; q++) acc1[nj][q] = 0.f;

        #pragma unroll
        for (int ks = 0; ks < K1 / 16; ks++) {
            uint32_t a[4];
            int r  = wm * 16 + gq;
            int ko = ks * 8 + t4;
            a[0] = sA0[r * RSA + ko];
            a[1] = sA0[(r + 8) * RSA + ko];
            a[2] = sA0[r * RSA + ko + 4];
            a[3] = sA0[(r + 8) * RSA + ko + 4];
            #pragma unroll
            for (int nj = 0; nj < NJ1; nj++) {
                int nr = wn * (H1 / 2) + nj * 8 + gq;
                uint32_t b[2] = { sW1[nr * RSA + ko], sW1[nr * RSA + ko + 4] };
                mma_bf16(acc1[nj], a, b);
            }
        }

        #pragma unroll
        for (int hf = 0; hf < 2; hf++) {
            int row = wm * 16 + gq + hf * 8;
            int gr  = row0 + row;
            float ind = 1.f;
            if (EPI1 == 1) ind = (g_deg[gr] > 0) ? 1.f : 0.f;
            #pragma unroll
            for (int nj = 0; nj < NJ1; nj++) {
                int c = wn * (H1 / 2) + nj * 8 + 2 * t4;
                float v0 = acc1[nj][hf * 2 + 0];
                float v1 = acc1[nj][hf * 2 + 1];
                if (EPI1 == 0) {
                    v0 += b1[c]; v1 += b1[c + 1];
                } else {
                    v0 = fmaxf(fmaf(v0 + b1[c]     * ind, gam[c]     * rsc, bet[c]),     0.f);
                    v1 = fmaxf(fmaf(v1 + b1[c + 1] * ind, gam[c + 1] * rsc, bet[c + 1]), 0.f);
                }
                *(bf162*)&sT[row * ST + c] = __floats2bfloat162_rn(v0, v1);
            }
        }
        __syncthreads();

        // ---- stage 2 (NSPLIT register slices) ----
        #pragma unroll
        for (int h = 0; h < NSPLIT; h++) {
            float acc2[NJ2H][4];
            #pragma unroll
            for (int nj = 0; nj < NJ2H; nj++)
                #pragma unroll
                for (int q = 0; q < 4; q++) acc2[nj][q] = 0.f;

            #pragma unroll
            for (int ks = 0; ks < H1 / 16; ks++) {
                uint32_t a[4];
                int r  = wm * 16 + gq;
                int kc = ks * 16 + 2 * t4;
                a[0] = *(const uint32_t*)&sT[r * ST + kc];
                a[1] = *(const uint32_t*)&sT[(r + 8) * ST + kc];
                a[2] = *(const uint32_t*)&sT[r * ST + kc + 8];
                a[3] = *(const uint32_t*)&sT[(r + 8) * ST + kc + 8];
                #pragma unroll
                for (int nj = 0; nj < NJ2H; nj++) {
                    int nr = wn * (WOUT / 2) + (h * NJ2H + nj) * 8 + gq;
                    uint32_t b[2] = { sW2[nr * RSB + ks * 8 + t4],
                                      sW2[nr * RSB + ks * 8 + t4 + 4] };
                    mma_bf16(acc2[nj], a, b);
                }
            }
            #pragma unroll
            for (int hf = 0; hf < 2; hf++) {
                int row = wm * 16 + gq + hf * 8;
                #pragma unroll
                for (int nj = 0; nj < NJ2H; nj++) {
                    int c = wn * (WOUT / 2) + (h * NJ2H + nj) * 8 + 2 * t4;
                    float v0 = acc2[nj][hf * 2 + 0] + b2[c];
                    float v1 = acc2[nj][hf * 2 + 1] + b2[c + 1];
                    *(uint16_t*)(sOut + row * SOS + c) = pack_e4m3(v0, v1);
                }
            }
        }
        __syncthreads();

        constexpr int CHW = WOUT / 16;
        #pragma unroll
        for (int t = 0; t < (64 * CHW + 255) / 256; t++) {
            int i = tid + t * 256;
            if (i < 64 * CHW) {
                int row = i / CHW, q = i % CHW;
                int gr  = row0 + row;
                if (gr < nrows)
                    *(uint4*)&AB[(size_t)gr * WOUT + q * 16] =
                        *(const uint4*)(sOut + row * SOS + q * 16);
            }
        }
    }
}

// ======== fused layer: pipelined in-kernel agg + 2-stage GEMM ========
// agg(tile t+1) -> sM[alt] overlaps GEMM(tile t) from sM[cur].
template <int K1, int H1, int WOUT, int MINB>
__global__ __launch_bounds__(256, MINB)
void layer_fused(const uint8_t* __restrict__ ABin, const bf16* __restrict__ W1t,
                 const float* __restrict__ b1, const float* __restrict__ gam,
                 const float* __restrict__ bet, const bf16* __restrict__ W2t,
                 const float* __restrict__ b2, uint8_t* __restrict__ ABout,
                 int nrows, int ntiles) {
    constexpr int RSA = K1 / 2 + 4;
    constexpr int RSB = H1 / 2 + 4;
    constexpr int ST  = H1 + 8;
    constexpr int NJ1 = H1 / 16;
    constexpr int NJ2 = WOUT / 16;
    constexpr int SOS = WOUT + 16;

    extern __shared__ uint32_t dyn[];
    uint32_t* sW1 = dyn;
    uint32_t* sW2 = sW1 + H1 * RSA;
    uint32_t* sM0 = sW2 + WOUT * RSB;
    uint32_t* sM1 = sM0 + 64 * RSA;
    bf16*     sT  = (bf16*)(sM1 + 64 * RSA);
    uint8_t*  sOut = (uint8_t*)(sT + 64 * ST);

    const int tid  = threadIdx.x;
    const int lane = tid & 31;
    const int wid  = tid >> 5;
    const int wm   = wid & 3;
    const int wn   = wid >> 2;
    const int gq   = lane >> 2;
    const int t4   = lane & 3;

    for (int i = tid; i < H1 * (K1 / 8); i += 256) {
        int row = i / (K1 / 8), q = i % (K1 / 8);
        *(uint4*)&sW1[row * RSA + q * 4] = *(const uint4*)&W1t[(size_t)row * K1 + q * 8];
    }
    for (int i = tid; i < WOUT * (H1 / 8); i += 256) {
        int row = i / (H1 / 8), q = i % (H1 / 8);
        *(uint4*)&sW2[row * RSB + q * 4] = *(const uint4*)&W2t[(size_t)row * H1 + q * 8];
    }
    if (blockIdx.x == 0 && tid < WOUT / 4)
        ((uint32_t*)ABout)[(size_t)nrows * (WOUT / 4) + tid] = 0xFEFEFEFEu;

    if ((int)blockIdx.x < ntiles)
        agg_tile<K1, RSA>(ABin, blockIdx.x * 64, sM0);
    __syncthreads();

    const float rsc = rsqrtf(1.f + 1e-5f);

    int k = 0;
    for (int tile = blockIdx.x; tile < ntiles; tile += gridDim.x, k ^= 1) {
        const int row0 = tile * 64;
        const uint32_t* cur = k ? sM1 : sM0;
        uint32_t*       alt = k ? sM0 : sM1;

        int tn = tile + gridDim.x;
        if (tn < ntiles) agg_tile<K1, RSA>(ABin, tn * 64, alt);

        // ---- stage 1 from cur ----
        float acc1[NJ1][4];
        #pragma unroll
        for (int nj = 0; nj < NJ1; nj++)
            #pragma unroll
            for (int q = 0; q < 4; q++) acc1[nj][q] = 0.f;

        #pragma unroll
        for (int ks = 0; ks < K1 / 16; ks++) {
            uint32_t a[4];
            int r  = wm * 16 + gq;
            int ko = ks * 8 + t4;
            a[0] = cur[r * RSA + ko];
            a[1] = cur[(r + 8) * RSA + ko];
            a[2] = cur[r * RSA + ko + 4];
            a[3] = cur[(r + 8) * RSA + ko + 4];
            #pragma unroll
            for (int nj = 0; nj < NJ1; nj++) {
                int nr = wn * (H1 / 2) + nj * 8 + gq;
                uint32_t b[2] = { sW1[nr * RSA + ko], sW1[nr * RSA + ko + 4] };
                mma_bf16(acc1[nj], a, b);
            }
        }

        #pragma unroll
        for (int hf = 0; hf < 2; hf++) {
            int row = wm * 16 + gq + hf * 8;
            int gr  = row0 + row;
            float ind = (g_deg[gr] > 0) ? 1.f : 0.f;
            #pragma unroll
            for (int nj = 0; nj < NJ1; nj++) {
                int c = wn * (H1 / 2) + nj * 8 + 2 * t4;
                float v0 = acc1[nj][hf * 2 + 0];
                float v1 = acc1[nj][hf * 2 + 1];
                v0 = fmaxf(fmaf(v0 + b1[c]     * ind, gam[c]     * rsc, bet[c]),     0.f);
                v1 = fmaxf(fmaf(v1 + b1[c + 1] * ind, gam[c + 1] * rsc, bet[c + 1]), 0.f);
                *(bf162*)&sT[row * ST + c] = __floats2bfloat162_rn(v0, v1);
            }
        }
        __syncthreads();

        // ---- stage 2 ----
        float acc2[NJ2][4];
        #pragma unroll
        for (int nj = 0; nj < NJ2; nj++)
            #pragma unroll
            for (int q = 0; q < 4; q++) acc2[nj][q] = 0.f;

        #pragma unroll
        for (int ks = 0; ks < H1 / 16; ks++) {
            uint32_t a[4];
            int r  = wm * 16 + gq;
            int kc = ks * 16 + 2 * t4;
            a[0] = *(const uint32_t*)&sT[r * ST + kc];
            a[1] = *(const uint32_t*)&sT[(r + 8) * ST + kc];
            a[2] = *(const uint32_t*)&sT[r * ST + kc + 8];
            a[3] = *(const uint32_t*)&sT[(r + 8) * ST + kc + 8];
            #pragma unroll
            for (int nj = 0; nj < NJ2; nj++) {
                int nr = wn * (WOUT / 2) + nj * 8 + gq;
                uint32_t b[2] = { sW2[nr * RSB + ks * 8 + t4],
                                  sW2[nr * RSB + ks * 8 + t4 + 4] };
                mma_bf16(acc2[nj], a, b);
            }
        }

        #pragma unroll
        for (int hf = 0; hf < 2; hf++) {
            int row = wm * 16 + gq + hf * 8;
            #pragma unroll
            for (int nj = 0; nj < NJ2; nj++) {
                int c = wn * (WOUT / 2) + nj * 8 + 2 * t4;
                float v0 = acc2[nj][hf * 2 + 0] + b2[c];
                float v1 = acc2[nj][hf * 2 + 1] + b2[c + 1];
                *(uint16_t*)(sOut + row * SOS + c) = pack_e4m3(v0, v1);
            }
        }
        __syncthreads();

        constexpr int CHW = WOUT / 16;
        #pragma unroll
        for (int t = 0; t < (64 * CHW + 255) / 256; t++) {
            int i = tid + t * 256;
            if (i < 64 * CHW) {
                int row = i / CHW, q = i % CHW;
                int gr  = row0 + row;
                if (gr < nrows)
                    *(uint4*)&ABout[(size_t)gr * WOUT + q * 16] =
                        *(const uint4*)(sOut + row * SOS + q * 16);
            }
        }
    }
}

// ======== fused last layer: pipelined agg + GEMM + BN/relu + pool ========
template <int K1, int MINB>   // K1 = 32, H = 32
__global__ __launch_bounds__(256, MINB)
void last_fused(const uint8_t* __restrict__ ABin, const bf16* __restrict__ Wt,
                const float* __restrict__ bias, const float* __restrict__ gam,
                const float* __restrict__ bet, const int* __restrict__ batch,
                int nrows, int ntiles) {
    constexpr int H   = 32;
    constexpr int RSA = K1 / 2 + 4;
    constexpr int NJ1 = H / 16;

    extern __shared__ uint32_t dyn[];
    uint32_t* sW  = dyn;                 // H * RSA
    uint32_t* sM0 = sW + H * RSA;
    uint32_t* sM1 = sM0 + 64 * RSA;

    const int tid  = threadIdx.x;
    const int lane = tid & 31;
    const int wid  = tid >> 5;
    const int wm   = wid & 3;
    const int wn   = wid >> 2;
    const int gq   = lane >> 2;
    const int t4   = lane & 3;

    for (int i = tid; i < H * (K1 / 8); i += 256) {
        int row = i / (K1 / 8), q = i % (K1 / 8);
        *(uint4*)&sW[row * RSA + q * 4] = *(const uint4*)&Wt[(size_t)row * K1 + q * 8];
    }

    if ((int)blockIdx.x < ntiles)
        agg_tile<K1, RSA>(ABin, blockIdx.x * 64, sM0);
    __syncthreads();

    const float rsc = rsqrtf(1.f + 1e-5f);

    int k = 0;
    for (int tile = blockIdx.x; tile < ntiles; tile += gridDim.x, k ^= 1) {
        const int row0 = tile * 64;
        const uint32_t* cur = k ? sM1 : sM0;
        uint32_t*       alt = k ? sM0 : sM1;

        int tn = tile + gridDim.x;
        if (tn < ntiles) agg_tile<K1, RSA>(ABin, tn * 64, alt);

        float acc1[NJ1][4];
        #pragma unroll
        for (int nj = 0; nj < NJ1; nj++)
            #pragma unroll
            for (int q = 0; q < 4; q++) acc1[nj][q] = 0.f;

        #pragma unroll
        for (int ks = 0; ks < K1 / 16; ks++) {
            uint32_t a[4];
            int r  = wm * 16 + gq;
            int ko = ks * 8 + t4;
            a[0] = cur[r * RSA + ko];
            a[1] = cur[(r + 8) * RSA + ko];
            a[2] = cur[r * RSA + ko + 4];
            a[3] = cur[(r + 8) * RSA + ko + 4];
            #pragma unroll
            for (int nj = 0; nj < NJ1; nj++) {
                int nr = wn * (H / 2) + nj * 8 + gq;
                uint32_t b[2] = { sW[nr * RSA + ko], sW[nr * RSA + ko + 4] };
                mma_bf16(acc1[nj], a, b);
            }
        }

        #pragma unroll
        for (int hf = 0; hf < 2; hf++) {
            int row = wm * 16 + gq + hf * 8;
            int gr  = row0 + row;
            if (gr >= nrows) continue;
            float ind = (g_deg[gr] > 0) ? 1.f : 0.f;
            int pb = batch[gr] * 32;
            #pragma unroll
            for (int nj = 0; nj < NJ1; nj++) {
                int c = wn * (H / 2) + nj * 8 + 2 * t4;
                float v0 = acc1[nj][hf * 2 + 0];
                float v1 = acc1[nj][hf * 2 + 1];
                v0 = fmaxf(fmaf(v0 + bias[c]     * ind, gam[c]     * rsc, bet[c]),     0.f);
                v1 = fmaxf(fmaf(v1 + bias[c + 1] * ind, gam[c + 1] * rsc, bet[c + 1]), 0.f);
                atomicAdd(&g_pool[pb + c],     v0);
                atomicAdd(&g_pool[pb + c + 1], v1);
            }
        }
        __syncthreads();
    }
}

// ------- standalone edge aggregation (layer 1, H=128): AB fp8 -> g_M bf16 ---
template <int H>
__global__ void edge_agg_kernel(int n) {
    int gw   = (blockIdx.x * blockDim.x + threadIdx.x) >> 5;
    int lane = threadIdx.x & 31;
    int w    = gw;                     // H=128: one warp per node
    if (w >= n) return;
    uint2 ov = agg_node<H>(g_AB, w, lane);
    *(uint2*)&g_M[(size_t)w * H + lane * 4] = ov;
}

// ---- classifier + state recycle (zero g_deg/g_total for next launch) ----
__global__ void final_kernel(const float* __restrict__ Wfc,
                             const float* __restrict__ bfc,
                             float* __restrict__ out, int g, int n) {
    int t = blockIdx.x * blockDim.x + threadIdx.x;
    int nt = gridDim.x * blockDim.x;
    for (int i = t; i < n; i += nt) g_deg[i] = 0;
    if (t == 0) g_total = 0;
    if (t >= g * 5) return;
    int gi = t / 5, o = t % 5;
    float inv = 1.f / fmaxf(g_gcnt[gi], 1.f);
    float z = bfc[o];
    #pragma unroll
    for (int k = 0; k < 32; k++)
        z = fmaf(g_pool[gi * 32 + k] * inv, Wfc[k * 5 + o], z);
    out[t] = 1.f / (1.f + expf(-z));
}

// ---------------- launch ----------------
static inline int cdiv(int a, int b) { return (a + b - 1) / b; }

template <int K1, int H1, int WOUT>
static inline int fg_smem() {
    int rsa = K1 / 2 + 4, rsb = H1 / 2 + 4, st = H1 + 8, sos = WOUT + 16;
    return (H1 * rsa + WOUT * rsb + 64 * rsa) * 4 + 64 * st * 2 + 64 * sos;
}
template <int K1, int H1, int WOUT>
static inline int lf_smem() {
    int rsa = K1 / 2 + 4, rsb = H1 / 2 + 4, st = H1 + 8, sos = WOUT + 16;
    return (H1 * rsa + WOUT * rsb + 2 * 64 * rsa) * 4 + 64 * st * 2 + 64 * sos;
}

extern "C" void kernel_launch(void* const* d_in, const int* in_sizes, int n_in,
                              void* d_out, int out_size) {
    const float* x     = (const float*)d_in[0];
    const float* Wn    = (const float*)d_in[4];
    const float* bnode = (const float*)d_in[5];
    const float* W1a   = (const float*)d_in[6];
    const float* b1a   = (const float*)d_in[7];
    const float* W1b   = (const float*)d_in[8];
    const float* b1b   = (const float*)d_in[9];
    const float* W2a   = (const float*)d_in[10];
    const float* b2a   = (const float*)d_in[11];
    const float* W2b   = (const float*)d_in[12];
    const float* b2b   = (const float*)d_in[13];
    const float* W3a   = (const float*)d_in[14];
    const float* b3a   = (const float*)d_in[15];
    const float* W3b   = (const float*)d_in[16];
    const float* b3b   = (const float*)d_in[17];
    const float* gm1   = (const float*)d_in[18];
    const float* bt1   = (const float*)d_in[19];
    const float* gm2   = (const float*)d_in[20];
    const float* bt2   = (const float*)d_in[21];
    const float* gm3   = (const float*)d_in[22];
    const float* bt3   = (const float*)d_in[23];
    const float* Wfc   = (const float*)d_in[24];
    const float* bfc   = (const float*)d_in[25];
    const int*   ei    = (const int*)d_in[26];
    const int*   batch = (const int*)d_in[27];

    const int n = in_sizes[0] / 32;
    const int e = in_sizes[26] / 2;
    const int g = out_size / 5;

    const int* src = ei;
    const int* dst = ei + e;

    bf16 *M, *Wtn, *Wct1, *Wt1b, *Wct2, *Wt2b, *Wct3, *Wt3b;
    uint8_t* AB;
    float *bc1, *bc2, *bc3;
    cudaGetSymbolAddress((void**)&M,    g_M);
    cudaGetSymbolAddress((void**)&AB,   g_AB);
    cudaGetSymbolAddress((void**)&Wtn,  g_Wtn);
    cudaGetSymbolAddress((void**)&Wct1, g_Wct1);
    cudaGetSymbolAddress((void**)&Wt1b, g_Wt1b);
    cudaGetSymbolAddress((void**)&Wct2, g_Wct2);
    cudaGetSymbolAddress((void**)&Wt2b, g_Wt2b);
    cudaGetSymbolAddress((void**)&Wct3, g_Wct3);
    cudaGetSymbolAddress((void**)&Wt3b, g_Wt3b);
    cudaGetSymbolAddress((void**)&bc1,  g_bc1);
    cudaGetSymbolAddress((void**)&bc2,  g_bc2);
    cudaGetSymbolAddress((void**)&bc3,  g_bc3);
    uint8_t* ABM = (uint8_t*)M;          // g_M region reused for AB3 fp8 [N,64]

    const int sm1 = fg_smem<32, 64, 256>();
    const int sm2 = fg_smem<128, 128, 128>();
    const int sm3 = lf_smem<64, 64, 64>();
    const int sm4 = lf_smem<32, 32, 0>() - 64 * (32 + 8) * 2;  // no sT/sOut; approx upper bound kept simple
    cudaFuncSetAttribute((const void*)fused_gemm<32, 64, 256, 0, 2, 3, true, true>,
                         cudaFuncAttributeMaxDynamicSharedMemorySize, sm1);
    cudaFuncSetAttribute((const void*)fused_gemm<128, 128, 128, 1, 1, 2, false, false>,
                         cudaFuncAttributeMaxDynamicSharedMemorySize, sm2);
    cudaFuncSetAttribute((const void*)layer_fused<64, 64, 64, 3>,
                         cudaFuncAttributeMaxDynamicSharedMemorySize, sm3);
    cudaFuncSetAttribute((const void*)last_fused<32, 3>,
                         cudaFuncAttributeMaxDynamicSharedMemorySize, sm4);

    init_kernel<<<cdiv(e, 256), 256>>>(dst, n, e, g,
        Wn, W1a, b1a, W1b, W2a, b2a, W2b, W3a, b3a, W3b);
    alloc_kernel<<<cdiv(n, 256), 256>>>(n, batch);

    const int ntiles = cdiv(n, 64);
    const int PG2 = 296, PG3 = 444;
    const int gP2 = (ntiles < PG2) ? ntiles : PG2;
    const int gP3 = (ntiles < PG3) ? ntiles : PG3;

    // layer 1 + edge scatter: x(f32) -> h0 -> AB1 fp8[N,256]
    fused_gemm<32, 64, 256, 0, 2, 3, true, true><<<gP3, 256, sm1>>>(
        x, Wtn, bnode, nullptr, nullptr, Wct1, bc1, AB, src, dst, e, n, ntiles);
    edge_agg_kernel<128><<<cdiv(n, 8), 256>>>(n);

    // layer 2: M1 -> h1 -> AB2 fp8[N,128]
    fused_gemm<128, 128, 128, 1, 1, 2, false, false><<<gP2, 256, sm2>>>(
        M, Wt1b, b1b, gm1, bt1, Wct2, bc2, AB, nullptr, nullptr, 0, n, ntiles);

    // layer 3 fused: agg(AB2,H=64) + [BNrelu GEMM -> AB3 fp8[N,64] in g_M]
    layer_fused<64, 64, 64, 3><<<gP3, 256, sm3>>>(
        AB, Wt2b, b2b, gm2, bt2, Wct3, bc3, ABM, n, ntiles);

    // last fused: agg(AB3,H=32) + BNrelu GEMM -> pool atomics
    last_fused<32, 3><<<gP3, 256, sm4>>>(
        ABM, Wt3b, b3b, gm3, bt3, batch, n, ntiles);

    final_kernel<<<cdiv(g * 5, 256), 256>>>(Wfc, bfc, (float*)d_out, g, n);
}

// round 16
// speedup vs baseline: 1.0367x; 1.0367x over previous
#include <cuda_runtime.h>
#include <cuda_bf16.h>
#include <cuda_fp16.h>
#include <math.h>
#include <stdint.h>

// ---------------- problem-size bounds ----------------
#define NMAX 50048
#define EMAX 760064            // E + up to 3 pad slots per node
#define GMAX 2048

typedef __nv_bfloat16 bf16;
typedef __nv_bfloat162 bf162;

// ---------------- scratch (device globals) ----------------
// Invariant: g_deg and g_total are zero at entry of every launch.
__device__ int      g_deg[NMAX];
__device__ int      g_off[NMAX];
__device__ int      g_pos[NMAX];
__device__ int      g_total;
__device__ uint16_t g_srt_src[EMAX];

__device__ bf16    g_M [NMAX * 128];         // aggregated means (bf16)
__device__ uint8_t g_AB[(NMAX + 1) * 256];   // fp8 e4m3 AB (+pad row)

// bf16 weights, transposed to [H][K] (n-major)
__device__ bf16  g_Wtn [64 * 32];
__device__ bf16  g_Wct1[256 * 64];
__device__ bf16  g_Wt1b[128 * 128];
__device__ bf16  g_Wct2[128 * 128];
__device__ bf16  g_Wt2b[64 * 64];
__device__ bf16  g_Wct3[64 * 64];
__device__ bf16  g_Wt3b[32 * 32];
__device__ float g_bc1[256], g_bc2[128], g_bc3[64];

__device__ float g_pool[GMAX * 32];
__device__ float g_gcnt[GMAX];

// ---------------- fp8 / async helpers ----------------
__device__ __forceinline__ uint16_t pack_e4m3(float v0, float v1) {
    uint16_t r;
    asm("cvt.rn.satfinite.e4m3x2.f32 %0, %1, %2;" : "=h"(r) : "f"(v1), "f"(v0));
    return r;
}
__device__ __forceinline__ __half2 e4_h2(uint16_t u) {
    uint32_t h;
    asm("cvt.rn.f16x2.e4m3x2 %0, %1;" : "=r"(h) : "h"(u));
    return *(__half2*)&h;
}
__device__ __forceinline__ void cp16(uint32_t saddr, const void* g) {
    asm volatile("cp.async.cg.shared.global [%0], [%1], 16;" :: "r"(saddr), "l"(g));
}
__device__ __forceinline__ void cp_commit() { asm volatile("cp.async.commit_group;"); }
__device__ __forceinline__ void cp_wait0()  { asm volatile("cp.async.wait_group 0;"); }

// -------- init: zero pool/gcnt, histogram degrees, prep weights --------
__global__ void init_kernel(const int* __restrict__ dst, int n, int e, int g,
                            const float* Wn,  const float* W1a, const float* b1a,
                            const float* W1b, const float* W2a, const float* b2a,
                            const float* W2b, const float* W3a, const float* b3a,
                            const float* W3b) {
    int i = blockIdx.x * blockDim.x + threadIdx.x;
    if (i < g * 32)  g_pool[i] = 0.f;
    if (i < g)       g_gcnt[i] = 0.f;
    if (i < e)       atomicAdd(&g_deg[dst[i]], 1);

    const int S0 = 64 * 32;
    const int S1 = 256 * 64;
    const int S2 = 128 * 128;
    const int S3 = 128 * 128;
    const int S4 = 64 * 64;
    const int S5 = 64 * 64;
    const int S6 = 32 * 32;
    const int TOT = S0 + S1 + S2 + S3 + S4 + S5 + S6;
    if (i < TOT) {
        int j = i;
        if (j < S0) { int c = j / 32, k = j % 32;
            g_Wtn[j] = __float2bfloat16(Wn[k * 64 + c]); return; } j -= S0;
        if (j < S1) { int c = j / 64, k = j % 64;
            float v = (c < 128) ? W1a[k * 128 + c] - W1a[(k + 64) * 128 + c]
                                : W1a[(k + 64) * 128 + (c - 128)];
            g_Wct1[j] = __float2bfloat16(v);
            if (k == 0) g_bc1[c] = (c < 128) ? b1a[c] : 0.f;
            return; } j -= S1;
        if (j < S2) { int c = j / 128, k = j % 128;
            g_Wt1b[j] = __float2bfloat16(W1b[k * 128 + c]); return; } j -= S2;
        if (j < S3) { int c = j / 128, k = j % 128;
            float v = (c < 64) ? W2a[k * 64 + c] - W2a[(k + 128) * 64 + c]
                               : W2a[(k + 128) * 64 + (c - 64)];
            g_Wct2[j] = __float2bfloat16(v);
            if (k == 0) g_bc2[c] = (c < 64) ? b2a[c] : 0.f;
            return; } j -= S3;
        if (j < S4) { int c = j / 64, k = j % 64;
            g_Wt2b[j] = __float2bfloat16(W2b[k * 64 + c]); return; } j -= S4;
        if (j < S5) { int c = j / 64, k = j % 64;
            float v = (c < 32) ? W3a[k * 32 + c] - W3a[(k + 64) * 32 + c]
                               : W3a[(k + 64) * 32 + (c - 32)];
            g_Wct3[j] = __float2bfloat16(v);
            if (k == 0) g_bc3[c] = (c < 32) ? b3a[c] : 0.f;
            return; } j -= S5;
        { int c = j / 32, k = j % 32;
            g_Wt3b[j] = __float2bfloat16(W3b[k * 32 + c]); }
    }
}

// Warp-aggregated range allocation (sizes rounded to multiples of 4) +
// pad-slot fill (sentinel index = n) + per-graph node counts.
__global__ void alloc_kernel(int n, const int* __restrict__ batch) {
    int i = blockIdx.x * blockDim.x + threadIdx.x;
    int lane = threadIdx.x & 31;
    int d  = (i < n) ? g_deg[i] : 0;
    int dr = (d + 3) & ~3;
    int pre = dr;
    #pragma unroll
    for (int s = 1; s < 32; s <<= 1) {
        int t = __shfl_up_sync(0xffffffffu, pre, s);
        if (lane >= s) pre += t;
    }
    int wsum = __shfl_sync(0xffffffffu, pre, 31);
    int base = 0;
    if (lane == 31) base = atomicAdd(&g_total, wsum);
    base = __shfl_sync(0xffffffffu, base, 31);
    int off = base + pre - dr;
    if (i < n) {
        g_off[i] = off; g_pos[i] = off;
        for (int p = d; p < dr; p++) g_srt_src[off + p] = (uint16_t)n;
        atomicAdd(&g_gcnt[batch[i]], 1.f);
    }
}

// ---------------- bf16 mma ----------------
__device__ __forceinline__ void mma_bf16(float* c, const uint32_t* a, const uint32_t* b) {
    asm volatile(
        "mma.sync.aligned.m16n8k16.row.col.f32.bf16.bf16.f32 "
        "{%0,%1,%2,%3}, {%4,%5,%6,%7}, {%8,%9}, {%0,%1,%2,%3};"
        : "+f"(c[0]), "+f"(c[1]), "+f"(c[2]), "+f"(c[3])
        : "r"(a[0]), "r"(a[1]), "r"(a[2]), "r"(a[3]), "r"(b[0]), "r"(b[1]));
}

// ======== persistent fused 2-stage GEMM (+ optional edge scatter) ====
template <int K1, int H1, int WOUT, int EPI1, int NSPLIT, int MINB, bool SCAT, bool XF32>
__global__ __launch_bounds__(256, MINB)
void fused_gemm(const void* __restrict__ Xv, const bf16* __restrict__ W1t,
                const float* __restrict__ b1, const float* __restrict__ gam,
                const float* __restrict__ bet, const bf16* __restrict__ W2t,
                const float* __restrict__ b2, uint8_t* __restrict__ AB,
                const int* __restrict__ esrc, const int* __restrict__ edst,
                int ne, int nrows, int ntiles) {
    constexpr int RSA  = K1 / 2 + 4;
    constexpr int RSB  = H1 / 2 + 4;
    constexpr int ST   = H1 + 8;
    constexpr int NJ1  = H1 / 16;
    constexpr int NJ2  = WOUT / 16;
    constexpr int NJ2H = NJ2 / NSPLIT;
    constexpr int SOS  = WOUT + 16;
    constexpr int XC   = K1 / 8;

    extern __shared__ uint32_t dyn[];
    uint32_t* sW1 = dyn;
    uint32_t* sW2 = sW1 + H1 * RSA;
    uint32_t* sA0 = sW2 + WOUT * RSB;
    bf16*     sT  = (bf16*)(sA0 + 64 * RSA);
    uint8_t*  sOut = (uint8_t*)(sT + 64 * ST);

    const int tid  = threadIdx.x;
    const int lane = tid & 31;
    const int wid  = tid >> 5;
    const int wm   = wid & 3;
    const int wn   = wid >> 2;
    const int gq   = lane >> 2;
    const int t4   = lane & 3;

    for (int i = tid; i < H1 * (K1 / 8); i += 256) {
        int row = i / (K1 / 8), q = i % (K1 / 8);
        *(uint4*)&sW1[row * RSA + q * 4] = *(const uint4*)&W1t[(size_t)row * K1 + q * 8];
    }
    for (int i = tid; i < WOUT * (H1 / 8); i += 256) {
        int row = i / (H1 / 8), q = i % (H1 / 8);
        *(uint4*)&sW2[row * RSB + q * 4] = *(const uint4*)&W2t[(size_t)row * H1 + q * 8];
    }
    if (blockIdx.x == 0 && tid < WOUT / 4)
        ((uint32_t*)AB)[(size_t)nrows * (WOUT / 4) + tid] = 0xFEFEFEFEu;

    if (SCAT) {   // independent of GEMM; consumed next launch
        for (int i = blockIdx.x * 256 + tid; i < ne; i += gridDim.x * 256) {
            int p = atomicAdd(&g_pos[edst[i]], 1);
            g_srt_src[p] = (uint16_t)esrc[i];
        }
    }

    const uint32_t sA0a = (uint32_t)__cvta_generic_to_shared(sA0);
    const float rsc = rsqrtf(1.f + 1e-5f);

    for (int tile = blockIdx.x; tile < ntiles; tile += gridDim.x) {
        const int row0 = tile * 64;

        __syncthreads();       // prev consumers of sA/sOut done
        if (XF32) {
            const float* Xf = (const float*)Xv;
            for (int i = tid; i < 64 * (K1 / 4); i += 256) {
                int row = i / (K1 / 4), q = i % (K1 / 4);
                int gr = row0 + row;
                float4 v = make_float4(0.f, 0.f, 0.f, 0.f);
                if (gr < nrows) v = *(const float4*)&Xf[(size_t)gr * K1 + q * 4];
                bf162 p0 = __floats2bfloat162_rn(v.x, v.y);
                bf162 p1 = __floats2bfloat162_rn(v.z, v.w);
                uint2 u;
                u.x = *(uint32_t*)&p0;
                u.y = *(uint32_t*)&p1;
                *(uint2*)&sA0[row * RSA + q * 2] = u;
            }
        } else {
            const bf16* Xb = (const bf16*)Xv;
            for (int i = tid; i < 64 * XC; i += 256) {
                int row = i / XC, q = i % XC;
                cp16(sA0a + (uint32_t)(row * RSA + q * 4) * 4,
                     &Xb[(size_t)(row0 + row) * K1 + q * 8]);
            }
            cp_commit();
            cp_wait0();
        }
        __syncthreads();

        // ---- stage 1 ----
        float acc1[NJ1][4];
        #pragma unroll
        for (int nj = 0; nj < NJ1; nj++)
            #pragma unroll
            for (int q = 0; q < 4; q++) acc1[nj][q] = 0.f;

        #pragma unroll
        for (int ks = 0; ks < K1 / 16; ks++) {
            uint32_t a[4];
            int r  = wm * 16 + gq;
            int ko = ks * 8 + t4;
            a[0] = sA0[r * RSA + ko];
            a[1] = sA0[(r + 8) * RSA + ko];
            a[2] = sA0[r * RSA + ko + 4];
            a[3] = sA0[(r + 8) * RSA + ko + 4];
            #pragma unroll
            for (int nj = 0; nj < NJ1; nj++) {
                int nr = wn * (H1 / 2) + nj * 8 + gq;
                uint32_t b[2] = { sW1[nr * RSA + ko], sW1[nr * RSA + ko + 4] };
                mma_bf16(acc1[nj], a, b);
            }
        }

        #pragma unroll
        for (int hf = 0; hf < 2; hf++) {
            int row = wm * 16 + gq + hf * 8;
            int gr  = row0 + row;
            float ind = 1.f;
            if (EPI1 == 1) ind = (g_deg[gr] > 0) ? 1.f : 0.f;
            #pragma unroll
            for (int nj = 0; nj < NJ1; nj++) {
                int c = wn * (H1 / 2) + nj * 8 + 2 * t4;
                float v0 = acc1[nj][hf * 2 + 0];
                float v1 = acc1[nj][hf * 2 + 1];
                if (EPI1 == 0) {
                    v0 += b1[c]; v1 += b1[c + 1];
                } else {
                    v0 = fmaxf(fmaf(v0 + b1[c]     * ind, gam[c]     * rsc, bet[c]),     0.f);
                    v1 = fmaxf(fmaf(v1 + b1[c + 1] * ind, gam[c + 1] * rsc, bet[c + 1]), 0.f);
                }
                *(bf162*)&sT[row * ST + c] = __floats2bfloat162_rn(v0, v1);
            }
        }
        __syncthreads();

        // ---- stage 2 (NSPLIT register slices) ----
        #pragma unroll
        for (int h = 0; h < NSPLIT; h++) {
            float acc2[NJ2H][4];
            #pragma unroll
            for (int nj = 0; nj < NJ2H; nj++)
                #pragma unroll
                for (int q = 0; q < 4; q++) acc2[nj][q] = 0.f;

            #pragma unroll
            for (int ks = 0; ks < H1 / 16; ks++) {
                uint32_t a[4];
                int r  = wm * 16 + gq;
                int kc = ks * 16 + 2 * t4;
                a[0] = *(const uint32_t*)&sT[r * ST + kc];
                a[1] = *(const uint32_t*)&sT[(r + 8) * ST + kc];
                a[2] = *(const uint32_t*)&sT[r * ST + kc + 8];
                a[3] = *(const uint32_t*)&sT[(r + 8) * ST + kc + 8];
                #pragma unroll
                for (int nj = 0; nj < NJ2H; nj++) {
                    int nr = wn * (WOUT / 2) + (h * NJ2H + nj) * 8 + gq;
                    uint32_t b[2] = { sW2[nr * RSB + ks * 8 + t4],
                                      sW2[nr * RSB + ks * 8 + t4 + 4] };
                    mma_bf16(acc2[nj], a, b);
                }
            }
            #pragma unroll
            for (int hf = 0; hf < 2; hf++) {
                int row = wm * 16 + gq + hf * 8;
                #pragma unroll
                for (int nj = 0; nj < NJ2H; nj++) {
                    int c = wn * (WOUT / 2) + (h * NJ2H + nj) * 8 + 2 * t4;
                    float v0 = acc2[nj][hf * 2 + 0] + b2[c];
                    float v1 = acc2[nj][hf * 2 + 1] + b2[c + 1];
                    *(uint16_t*)(sOut + row * SOS + c) = pack_e4m3(v0, v1);
                }
            }
        }
        __syncthreads();

        constexpr int CHW = WOUT / 16;
        #pragma unroll
        for (int t = 0; t < (64 * CHW + 255) / 256; t++) {
            int i = tid + t * 256;
            if (i < 64 * CHW) {
                int row = i / CHW, q = i % CHW;
                int gr  = row0 + row;
                if (gr < nrows)
                    *(uint4*)&AB[(size_t)gr * WOUT + q * 16] =
                        *(const uint4*)(sOut + row * SOS + q * 16);
            }
        }
    }
}

// ======== last GEMM: pool += bnrelu(M3 @ W3b) (H=32) ========
__global__ __launch_bounds__(256)
void last_gemm(const bf16* __restrict__ X, const bf16* __restrict__ Wt,
               const float* __restrict__ bias, const float* __restrict__ gam,
               const float* __restrict__ bet, const int* __restrict__ batch,
               int nrows) {
    constexpr int K = 32, H = 32, BM = 256, RS = 20;
    __shared__ uint32_t sA[BM * RS];
    __shared__ uint32_t sB[H * RS];

    const int tid  = threadIdx.x;
    const int lane = tid & 31;
    const int wid  = tid >> 5;
    const int row0 = blockIdx.x * BM;
    const int gq   = lane >> 2;
    const int t4   = lane & 3;

    float acc[2][4][4];
    #pragma unroll
    for (int mi = 0; mi < 2; mi++)
        #pragma unroll
        for (int nj = 0; nj < 4; nj++)
            #pragma unroll
            for (int q = 0; q < 4; q++) acc[mi][nj][q] = 0.f;

    #pragma unroll
    for (int t = 0; t < 4; t++) {
        int i = tid + t * 256;
        int row = i >> 2, q = i & 3;
        int gr = row0 + row;
        uint4 v = make_uint4(0u, 0u, 0u, 0u);
        if (gr < nrows) v = *(const uint4*)&X[(size_t)gr * K + q * 8];
        *(uint4*)&sA[row * RS + q * 4] = v;
    }
    if (tid < H * 4) {
        int row = tid >> 2, q = tid & 3;
        *(uint4*)&sB[row * RS + q * 4] = *(const uint4*)&Wt[(size_t)row * K + q * 8];
    }
    __syncthreads();

    #pragma unroll
    for (int ks = 0; ks < 2; ks++) {
        uint32_t a[2][4], b[4][2];
        #pragma unroll
        for (int mi = 0; mi < 2; mi++) {
            int r = wid * 32 + mi * 16 + gq;
            a[mi][0] = sA[r * RS + ks * 8 + t4];
            a[mi][1] = sA[(r + 8) * RS + ks * 8 + t4];
            a[mi][2] = sA[r * RS + ks * 8 + t4 + 4];
            a[mi][3] = sA[(r + 8) * RS + ks * 8 + t4 + 4];
        }
        #pragma unroll
        for (int nj = 0; nj < 4; nj++) {
            int nr = nj * 8 + gq;
            b[nj][0] = sB[nr * RS + ks * 8 + t4];
            b[nj][1] = sB[nr * RS + ks * 8 + t4 + 4];
        }
        #pragma unroll
        for (int mi = 0; mi < 2; mi++)
            #pragma unroll
            for (int nj = 0; nj < 4; nj++)
                mma_bf16(acc[mi][nj], a[mi], b[nj]);
    }

    const float rsc = rsqrtf(1.f + 1e-5f);
    #pragma unroll
    for (int mi = 0; mi < 2; mi++) {
        #pragma unroll
        for (int hf = 0; hf < 2; hf++) {
            int gr = row0 + wid * 32 + mi * 16 + gq + hf * 8;
            if (gr >= nrows) continue;
            float ind = (g_deg[gr] > 0) ? 1.f : 0.f;
            int pb = batch[gr] * 32;
            #pragma unroll
            for (int nj = 0; nj < 4; nj++) {
                int c = nj * 8 + 2 * t4;
                float v0 = acc[mi][nj][hf * 2 + 0];
                float v1 = acc[mi][nj][hf * 2 + 1];
                v0 = fmaxf(fmaf(v0 + bias[c]     * ind, gam[c]     * rsc, bet[c]),     0.f);
                v1 = fmaxf(fmaf(v1 + bias[c + 1] * ind, gam[c + 1] * rsc, bet[c + 1]), 0.f);
                atomicAdd(&g_pool[pb + c],     v0);
                atomicAdd(&g_pool[pb + c + 1], v1);
            }
        }
    }
}

// ------- edge aggregation: M[v] = mean_e relu(A[v]+B[src_e]); AB fp8 -------
// Each lane owns 8 fp8 values (uint2 loads); LPN = H/8 lanes per node.
template <int H>
__global__ void edge_agg_kernel(int n) {
    constexpr int LPN = H / 8;
    constexpr int NPW = 32 / LPN;
    int gw   = (blockIdx.x * blockDim.x + threadIdx.x) >> 5;
    int lane = threadIdx.x & 31;
    int sub  = lane / LPN;
    int sl   = lane % LPN;
    int w    = gw * NPW + sub;
    if (w >= n) return;

    const uint8_t* ABp   = g_AB;
    const uint8_t* Bbase = ABp + H + sl * 8;

    uint2 a64 = *(const uint2*)(ABp + (size_t)w * 2 * H + sl * 8);
    __half2 a0 = e4_h2((uint16_t)a64.x);
    __half2 a1 = e4_h2((uint16_t)(a64.x >> 16));
    __half2 a2 = e4_h2((uint16_t)a64.y);
    __half2 a3 = e4_h2((uint16_t)(a64.y >> 16));
    const __half2 one = __float2half2_rn(1.f);
    __half2 c0 = __float2half2_rn(0.f), c1 = c0, c2 = c0, c3 = c0;

    int st = g_off[w];
    int d  = g_deg[w];
    int dr = (d + 3) & ~3;

    for (int e = st; e < st + dr; e += 4) {
        uint2 iv = *(const uint2*)&g_srt_src[e];
        int s0 = iv.x & 0xffff, s1 = iv.x >> 16;
        int s2 = iv.y & 0xffff, s3 = iv.y >> 16;
        uint2 b0 = *(const uint2*)(Bbase + (size_t)s0 * 2 * H);
        uint2 b1 = *(const uint2*)(Bbase + (size_t)s1 * 2 * H);
        uint2 b2 = *(const uint2*)(Bbase + (size_t)s2 * 2 * H);
        uint2 b3 = *(const uint2*)(Bbase + (size_t)s3 * 2 * H);
        #pragma unroll
        for (int q = 0; q < 4; q++) {
            uint2 bq = (q == 0) ? b0 : (q == 1) ? b1 : (q == 2) ? b2 : b3;
            c0 = __hadd2(c0, __hfma2_relu(one, e4_h2((uint16_t)bq.x), a0));
            c1 = __hadd2(c1, __hfma2_relu(one, e4_h2((uint16_t)(bq.x >> 16)), a1));
            c2 = __hadd2(c2, __hfma2_relu(one, e4_h2((uint16_t)bq.y), a2));
            c3 = __hadd2(c3, __hfma2_relu(one, e4_h2((uint16_t)(bq.y >> 16)), a3));
        }
    }

    float2 f0 = __half22float2(c0);
    float2 f1 = __half22float2(c1);
    float2 f2 = __half22float2(c2);
    float2 f3 = __half22float2(c3);
    float inv = 1.f / (float)max(d, 1);
    bf162 o0 = __floats2bfloat162_rn(f0.x * inv, f0.y * inv);
    bf162 o1 = __floats2bfloat162_rn(f1.x * inv, f1.y * inv);
    bf162 o2 = __floats2bfloat162_rn(f2.x * inv, f2.y * inv);
    bf162 o3 = __floats2bfloat162_rn(f3.x * inv, f3.y * inv);
    uint4 ov;
    ov.x = *(uint32_t*)&o0;
    ov.y = *(uint32_t*)&o1;
    ov.z = *(uint32_t*)&o2;
    ov.w = *(uint32_t*)&o3;
    *(uint4*)&g_M[(size_t)w * H + sl * 8] = ov;
}

// ---- classifier + state recycle (zero g_deg/g_total for next launch) ----
__global__ void final_kernel(const float* __restrict__ Wfc,
                             const float* __restrict__ bfc,
                             float* __restrict__ out, int g, int n) {
    int t = blockIdx.x * blockDim.x + threadIdx.x;
    int nt = gridDim.x * blockDim.x;
    for (int i = t; i < n; i += nt) g_deg[i] = 0;
    if (t == 0) g_total = 0;
    if (t >= g * 5) return;
    int gi = t / 5, o = t % 5;
    float inv = 1.f / fmaxf(g_gcnt[gi], 1.f);
    float z = bfc[o];
    #pragma unroll
    for (int k = 0; k < 32; k++)
        z = fmaf(g_pool[gi * 32 + k] * inv, Wfc[k * 5 + o], z);
    out[t] = 1.f / (1.f + expf(-z));
}

// ---------------- launch ----------------
static inline int cdiv(int a, int b) { return (a + b - 1) / b; }

template <int K1, int H1, int WOUT>
static inline int fg_smem() {
    int rsa = K1 / 2 + 4, rsb = H1 / 2 + 4, st = H1 + 8, sos = WOUT + 16;
    return (H1 * rsa + WOUT * rsb + 64 * rsa) * 4 + 64 * st * 2 + 64 * sos;
}

extern "C" void kernel_launch(void* const* d_in, const int* in_sizes, int n_in,
                              void* d_out, int out_size) {
    const float* x     = (const float*)d_in[0];
    const float* Wn    = (const float*)d_in[4];
    const float* bnode = (const float*)d_in[5];
    const float* W1a   = (const float*)d_in[6];
    const float* b1a   = (const float*)d_in[7];
    const float* W1b   = (const float*)d_in[8];
    const float* b1b   = (const float*)d_in[9];
    const float* W2a   = (const float*)d_in[10];
    const float* b2a   = (const float*)d_in[11];
    const float* W2b   = (const float*)d_in[12];
    const float* b2b   = (const float*)d_in[13];
    const float* W3a   = (const float*)d_in[14];
    const float* b3a   = (const float*)d_in[15];
    const float* W3b   = (const float*)d_in[16];
    const float* b3b   = (const float*)d_in[17];
    const float* gm1   = (const float*)d_in[18];
    const float* bt1   = (const float*)d_in[19];
    const float* gm2   = (const float*)d_in[20];
    const float* bt2   = (const float*)d_in[21];
    const float* gm3   = (const float*)d_in[22];
    const float* bt3   = (const float*)d_in[23];
    const float* Wfc   = (const float*)d_in[24];
    const float* bfc   = (const float*)d_in[25];
    const int*   ei    = (const int*)d_in[26];
    const int*   batch = (const int*)d_in[27];

    const int n = in_sizes[0] / 32;
    const int e = in_sizes[26] / 2;
    const int g = out_size / 5;

    const int* src = ei;
    const int* dst = ei + e;

    bf16 *M, *Wtn, *Wct1, *Wt1b, *Wct2, *Wt2b, *Wct3, *Wt3b;
    uint8_t* AB;
    float *bc1, *bc2, *bc3;
    cudaGetSymbolAddress((void**)&M,    g_M);
    cudaGetSymbolAddress((void**)&AB,   g_AB);
    cudaGetSymbolAddress((void**)&Wtn,  g_Wtn);
    cudaGetSymbolAddress((void**)&Wct1, g_Wct1);
    cudaGetSymbolAddress((void**)&Wt1b, g_Wt1b);
    cudaGetSymbolAddress((void**)&Wct2, g_Wct2);
    cudaGetSymbolAddress((void**)&Wt2b, g_Wt2b);
    cudaGetSymbolAddress((void**)&Wct3, g_Wct3);
    cudaGetSymbolAddress((void**)&Wt3b, g_Wt3b);
    cudaGetSymbolAddress((void**)&bc1,  g_bc1);
    cudaGetSymbolAddress((void**)&bc2,  g_bc2);
    cudaGetSymbolAddress((void**)&bc3,  g_bc3);

    const int sm1 = fg_smem<32, 64, 256>();
    const int sm2 = fg_smem<128, 128, 128>();
    const int sm3 = fg_smem<64, 64, 64>();
    cudaFuncSetAttribute((const void*)fused_gemm<32, 64, 256, 0, 2, 3, true, true>,
                         cudaFuncAttributeMaxDynamicSharedMemorySize, sm1);
    cudaFuncSetAttribute((const void*)fused_gemm<128, 128, 128, 1, 1, 2, false, false>,
                         cudaFuncAttributeMaxDynamicSharedMemorySize, sm2);
    cudaFuncSetAttribute((const void*)fused_gemm<64, 64, 64, 1, 1, 3, false, false>,
                         cudaFuncAttributeMaxDynamicSharedMemorySize, sm3);

    init_kernel<<<cdiv(e, 256), 256>>>(dst, n, e, g,
        Wn, W1a, b1a, W1b, W2a, b2a, W2b, W3a, b3a, W3b);
    alloc_kernel<<<cdiv(n, 256), 256>>>(n, batch);

    const int ntiles = cdiv(n, 64);
    const int PG2 = 296, PG3 = 444;
    const int gP2 = (ntiles < PG2) ? ntiles : PG2;
    const int gP3 = (ntiles < PG3) ? ntiles : PG3;

    // layer 1 + edge scatter: x(f32) -> h0 -> AB1 fp8[N,256]
    fused_gemm<32, 64, 256, 0, 2, 3, true, true><<<gP3, 256, sm1>>>(
        x, Wtn, bnode, nullptr, nullptr, Wct1, bc1, AB, src, dst, e, n, ntiles);
    edge_agg_kernel<128><<<cdiv(n, 16), 256>>>(n);     // 2 nodes/warp

    // layer 2: M1 -> h1 -> AB2 fp8[N,128]
    fused_gemm<128, 128, 128, 1, 1, 2, false, false><<<gP2, 256, sm2>>>(
        M, Wt1b, b1b, gm1, bt1, Wct2, bc2, AB, nullptr, nullptr, 0, n, ntiles);
    edge_agg_kernel<64><<<cdiv(n, 32), 256>>>(n);      // 4 nodes/warp

    // layer 3: M2 -> h2 -> AB3 fp8[N,64]
    fused_gemm<64, 64, 64, 1, 1, 3, false, false><<<gP3, 256, sm3>>>(
        M, Wt2b, b2b, gm2, bt2, Wct3, bc3, AB, nullptr, nullptr, 0, n, ntiles);
    edge_agg_kernel<32><<<cdiv(n, 64), 256>>>(n);      // 8 nodes/warp

    // pool GEMM + classifier
    last_gemm<<<cdiv(n, 256), 256>>>(M, Wt3b, b3b, gm3, bt3, batch, n);
    final_kernel<<<cdiv(g * 5, 256), 256>>>(Wfc, bfc, (float*)d_out, g, n);
}